// round 9
// baseline (speedup 1.0000x reference)
#include <cuda_runtime.h>
#include <cuda_fp16.h>
#include <cstdint>

// ============================================================================
// Single-term fp16 mma.sync implicit-GEMM conv, round 9.
// Same math/layout as round 8 (D = ah*bh, A=w*64 fp16, B=x fp16, ~2.9e-4).
// BK=64: each barrier interval processes TWO 32-k subtiles (layouts unchanged,
// prep_a unchanged). 36 chunks instead of 72 -> half the barriers, double the
// MMA run length hiding the B-gather and A-cp.async latency.
// ============================================================================

#define KTOT   2304
#define KCH    36            // 2304 / 64
#define NPIMG  2916
#define OUTIMG (512*NPIMG)
#define XIMG   (256*3136)

#define A_SUB       8192     // one 32-k A subtile (128 rows x 64B)
#define STAGE_BYTES 32768    // A 16KB (2 subtiles) + B 16KB (2 subtiles)
#define OFF_B       16384
#define OFF_KOFF    65536                  // after 2 stages
#define SMEM_BYTES  (OFF_KOFF + KTOT*4)    // 74752

// A (scaled x64, fp16) in swizzled subtile layout: [mt(4)][sub32(72)][8KB]
__device__ __align__(16) unsigned char g_asplit[4ull*72*8192];    // 2.4MB
// x as fp16
__device__ __align__(16) __half g_xh[32 * 256 * 56 * 56];         // 51.4MB

// ---------------------------------------------------------------------------
__device__ __forceinline__ uint32_t smem_u32(const void* p) {
    uint32_t a;
    asm("{ .reg .u64 t; cvta.to.shared.u64 t, %1; cvt.u32.u64 %0, t; }"
        : "=r"(a) : "l"(p));
    return a;
}
__device__ __forceinline__ void sts64(uint32_t addr, uint32_t a, uint32_t b) {
    asm volatile("st.shared.v2.b32 [%0], {%1, %2};" :: "r"(addr), "r"(a), "r"(b));
}
__device__ __forceinline__ void ldsm4(uint32_t a, uint32_t& r0, uint32_t& r1,
                                      uint32_t& r2, uint32_t& r3) {
    asm volatile("ldmatrix.sync.aligned.m8n8.x4.shared.b16 {%0,%1,%2,%3}, [%4];"
                 : "=r"(r0), "=r"(r1), "=r"(r2), "=r"(r3) : "r"(a));
}
__device__ __forceinline__ void mma_f16(float* c, const uint32_t* a,
                                        uint32_t b0, uint32_t b1) {
    asm volatile(
        "mma.sync.aligned.m16n8k16.row.col.f32.f16.f16.f32 "
        "{%0,%1,%2,%3}, {%4,%5,%6,%7}, {%8,%9}, {%0,%1,%2,%3};"
        : "+f"(c[0]), "+f"(c[1]), "+f"(c[2]), "+f"(c[3])
        : "r"(a[0]), "r"(a[1]), "r"(a[2]), "r"(a[3]), "r"(b0), "r"(b1));
}
__device__ __forceinline__ void cpasync16(uint32_t dst, const void* src) {
    asm volatile("cp.async.cg.shared.global [%0], [%1], 16;"
                 :: "r"(dst), "l"(src) : "memory");
}
__device__ __forceinline__ void cp_commit() {
    asm volatile("cp.async.commit_group;" ::: "memory");
}
__device__ __forceinline__ void cp_wait0() {
    asm volatile("cp.async.wait_group 0;" ::: "memory");
}

// ---------------------------------------------------------------------------
// prep kernels (unchanged from rounds 7/8)
// ---------------------------------------------------------------------------
__global__ void pack_x_kernel(const float* __restrict__ x) {
    int i = blockIdx.x * blockDim.x + threadIdx.x;   // 6422528 total
    float4 v = ((const float4*)x)[i];
    __half h0 = __float2half_rn(v.x), h1 = __float2half_rn(v.y);
    __half h2 = __float2half_rn(v.z), h3 = __float2half_rn(v.w);
    uint32_t w0 = (uint32_t)*(uint16_t*)&h0 | ((uint32_t)*(uint16_t*)&h1 << 16);
    uint32_t w1 = (uint32_t)*(uint16_t*)&h2 | ((uint32_t)*(uint16_t*)&h3 << 16);
    ((uint2*)g_xh)[i] = make_uint2(w0, w1);
}
__global__ void prep_a(const float* __restrict__ w) {
    int i = blockIdx.x * 256 + threadIdx.x;          // 147456 total
    int co = i / 288;
    int r  = i - co * 288;
    int ch = r >> 2, kq = r & 3;                     // ch = 32-k subtile index
    const float4* p = (const float4*)(w + (size_t)co * KTOT + ch * 32 + kq * 8);
    float4 v0 = p[0], v1 = p[1];
    __half a0 = __float2half_rn(v0.x * 64.f), a1 = __float2half_rn(v0.y * 64.f);
    __half a2 = __float2half_rn(v0.z * 64.f), a3 = __float2half_rn(v0.w * 64.f);
    __half a4 = __float2half_rn(v1.x * 64.f), a5 = __float2half_rn(v1.y * 64.f);
    __half a6 = __float2half_rn(v1.z * 64.f), a7 = __float2half_rn(v1.w * 64.f);
    uint32_t h0 = (uint32_t)*(uint16_t*)&a0 | ((uint32_t)*(uint16_t*)&a1 << 16);
    uint32_t h1 = (uint32_t)*(uint16_t*)&a2 | ((uint32_t)*(uint16_t*)&a3 << 16);
    uint32_t h2 = (uint32_t)*(uint16_t*)&a4 | ((uint32_t)*(uint16_t*)&a5 << 16);
    uint32_t h3 = (uint32_t)*(uint16_t*)&a6 | ((uint32_t)*(uint16_t*)&a7 << 16);
    int m = co & 127;
    size_t base = ((size_t)(co >> 7) * 72 + ch) * A_SUB
                + m * 64 + (((uint32_t)kq * 16) ^ ((((uint32_t)m >> 1) & 3) << 4));
    *(uint4*)(g_asplit + base) = make_uint4(h0, h1, h2, h3);
}

// ---------------------------------------------------------------------------
// B producer: one 64-k chunk = two 32-k subtiles.
// thread -> (row n = tid>>1, khalf = tid&1); per subtile 16 LDG.16 + 4 STS.64
// ---------------------------------------------------------------------------
__device__ __forceinline__ void load_b(
    int ch64, const __half* xb, uint32_t koffs, int khalf, uint16_t (&bx)[32])
{
    #pragma unroll
    for (int sub = 0; sub < 2; ++sub) {
        const uint32_t kb4 = koffs
            + (uint32_t)(ch64 * 64 + sub * 32 + khalf * 16) * 4;
        #pragma unroll
        for (int g = 0; g < 4; ++g) {
            uint32_t k0, k1, k2, k3;
            asm volatile("ld.shared.v4.b32 {%0,%1,%2,%3}, [%4];"
                         : "=r"(k0), "=r"(k1), "=r"(k2), "=r"(k3)
                         : "r"(kb4 + g * 16));
            bx[sub*16 + 4*g+0] = *(const uint16_t*)(xb + k0);
            bx[sub*16 + 4*g+1] = *(const uint16_t*)(xb + k1);
            bx[sub*16 + 4*g+2] = *(const uint16_t*)(xb + k2);
            bx[sub*16 + 4*g+3] = *(const uint16_t*)(xb + k3);
        }
    }
}
__device__ __forceinline__ void store_b(
    uint32_t bufb, const uint16_t (&bx)[32], int prow, int khalf, uint32_t pswz)
{
    const uint32_t kobase = (uint32_t)khalf * 32;
    #pragma unroll
    for (int sub = 0; sub < 2; ++sub) {
        const uint32_t sB = bufb + OFF_B + (uint32_t)sub * A_SUB
                          + (uint32_t)prow * 64;
        #pragma unroll
        for (int g = 0; g < 4; ++g) {
            uint32_t w0 = (uint32_t)bx[sub*16 + 4*g+0]
                        | ((uint32_t)bx[sub*16 + 4*g+1] << 16);
            uint32_t w1 = (uint32_t)bx[sub*16 + 4*g+2]
                        | ((uint32_t)bx[sub*16 + 4*g+3] << 16);
            sts64(sB + ((kobase + 8u * g) ^ pswz), w0, w1);
        }
    }
}

// ---------------------------------------------------------------------------
// MMA consumer on one 64-k chunk: 4 kb-steps over 2 subtiles.
// stage: [A sub0 8K][A sub1 8K][B sub0 8K][B sub1 8K]
// ---------------------------------------------------------------------------
__device__ __forceinline__ void mma_chunk(
    uint32_t bufb, float (&acc)[4][4][4],
    uint32_t aRowOff, uint32_t aKext, uint32_t aSwz,
    uint32_t bRowOff, uint32_t bKext, uint32_t bSwz)
{
    #pragma unroll
    for (int kb = 0; kb < 4; ++kb) {
        const uint32_t subOff = (uint32_t)(kb >> 1) * A_SUB;
        const uint32_t kb2 = (uint32_t)(kb & 1) * 32;
        const uint32_t aK = (kb2 + aKext) ^ aSwz;
        const uint32_t bK = (kb2 + bKext) ^ bSwz;

        uint32_t bh[8];
        const uint32_t bAddr = bufb + OFF_B + subOff + bRowOff + bK;
        ldsm4(bAddr,        bh[0], bh[1], bh[2], bh[3]);
        ldsm4(bAddr + 1024, bh[4], bh[5], bh[6], bh[7]);

        uint32_t a[16];
        const uint32_t aAddr = bufb + subOff + aRowOff + aK;
        #pragma unroll
        for (int am = 0; am < 4; ++am)
            ldsm4(aAddr + am * 1024, a[4*am], a[4*am+1], a[4*am+2], a[4*am+3]);

        #pragma unroll
        for (int am = 0; am < 4; ++am)
            #pragma unroll
            for (int an = 0; an < 4; ++an)
                mma_f16(acc[am][an], a + 4*am, bh[2*an], bh[2*an+1]);
    }
}

// ---------------------------------------------------------------------------
__global__ void __launch_bounds__(256, 2)
conv_mma_kernel(float* __restrict__ out)
{
    extern __shared__ char smem[];
    const uint32_t sb = smem_u32(smem);
    const int tid = threadIdx.x;
    const int bm = blockIdx.x;        // 0..3, fastest -> x gathers shared in L2
    const int bn = blockIdx.y;        // 0..728

    // im2col k -> x-offset table
    for (int k = tid; k < KTOT; k += 256) {
        int ci = k / 9, r9 = k - ci * 9;
        int kh = r9 / 3, kw = r9 - kh * 3;
        *(uint32_t*)(smem + OFF_KOFF + k * 4) = (uint32_t)(ci * 3136 + kh * 56 + kw);
    }

    // A copy: 64B per thread per 64-k chunk (two consecutive 8KB subtiles)
    const unsigned char* aBase = g_asplit + (size_t)bm * 72 * A_SUB
                               + (size_t)tid * 64;
    const uint32_t aOff = (uint32_t)tid * 64;

    // B producer invariants
    const int prow = tid >> 1, khalf = tid & 1;
    const int ng = bn * 128 + prow;
    const int bimg = ng / NPIMG;
    const int prem = ng - bimg * NPIMG;
    const int oh = prem / 54, ow = prem - oh * 54;
    const __half* xb = g_xh + (size_t)bimg * XIMG + oh * 56 + ow;
    const uint32_t pswz = (uint32_t)((prow >> 1) & 3) << 4;
    const uint32_t koffs = sb + OFF_KOFF;

    // MMA invariants: warp grid 2(m) x 4(n)
    const int lane = tid & 31, wid = tid >> 5;
    const int wm = wid & 1, wn = wid >> 1;
    const uint32_t aRowOff = (uint32_t)(wm * 64 + (lane & 15)) * 64;
    const uint32_t aKext   = (uint32_t)(lane >> 4) << 4;
    const uint32_t aSwz    = (uint32_t)(((lane & 15) >> 1) & 3) << 4;
    const uint32_t bRowOff = (uint32_t)(wn * 32 + (lane & 7) + ((lane >> 4) << 3)) * 64;
    const uint32_t bKext   = (uint32_t)((lane >> 3) & 1) << 4;
    const uint32_t bSwz    = (uint32_t)(((lane & 7) >> 1) & 3) << 4;

    float acc[4][4][4];
    #pragma unroll
    for (int i = 0; i < 4; ++i)
        #pragma unroll
        for (int j = 0; j < 4; ++j)
            #pragma unroll
            for (int r = 0; r < 4; ++r) acc[i][j][r] = 0.0f;

    __syncthreads();                      // koff table ready

    // prologue: stage 0
    #pragma unroll
    for (int j = 0; j < 4; ++j)
        cpasync16(sb + aOff + j * 16, aBase + j * 16);
    cp_commit();
    {
        uint16_t bx0[32];
        load_b(0, xb, koffs, khalf, bx0);
        store_b(sb, bx0, prow, khalf, pswz);
    }
    cp_wait0();
    __syncthreads();

    for (int ch = 0; ch < KCH; ++ch) {
        const uint32_t cur = sb + (uint32_t)(ch & 1) * STAGE_BYTES;
        const uint32_t nxt = sb + (uint32_t)((ch + 1) & 1) * STAGE_BYTES;
        const bool pre = (ch + 1 < KCH);

        uint16_t bx[32];
        if (pre) {
            load_b(ch + 1, xb, koffs, khalf, bx);      // LDGs issue, no wait
            const unsigned char* aSrc = aBase + (size_t)(ch + 1) * 2 * A_SUB;
            #pragma unroll
            for (int j = 0; j < 4; ++j)
                cpasync16(nxt + aOff + j * 16, aSrc + j * 16);
            cp_commit();
        }

        mma_chunk(cur, acc, aRowOff, aKext, aSwz, bRowOff, bKext, bSwz);

        if (pre)
            store_b(nxt, bx, prow, khalf, pswz);       // LDGs landed during MMA
        cp_wait0();
        __syncthreads();
    }

    // epilogue: scale by 1/64; acc[am][an] rows co, co+8 ; cols gn, gn+1
    const float s = 0.015625f;
    const int lane4 = lane >> 2, lane2 = (lane & 3) * 2;
    #pragma unroll
    for (int an = 0; an < 4; ++an) {
        const int gn = bn * 128 + wn * 32 + an * 8 + lane2;
        const int b2 = gn / NPIMG;
        const int r2 = gn - b2 * NPIMG;
        float* op = out + (size_t)b2 * OUTIMG + r2;
        #pragma unroll
        for (int am = 0; am < 4; ++am) {
            const int co = bm * 128 + wm * 64 + am * 16 + lane4;
            *(float2*)(op + (size_t)co * NPIMG) =
                make_float2(acc[am][an][0] * s, acc[am][an][1] * s);
            *(float2*)(op + (size_t)(co + 8) * NPIMG) =
                make_float2(acc[am][an][2] * s, acc[am][an][3] * s);
        }
    }
}

// ---------------------------------------------------------------------------
extern "C" void kernel_launch(void* const* d_in, const int* in_sizes, int n_in,
                              void* d_out, int out_size)
{
    const float* x = (const float*)d_in[0];   // [32,256,56,56]
    const float* w = (const float*)d_in[1];   // [512,256,3,3]
    float* out = (float*)d_out;               // [32,512,54,54]

    cudaFuncSetAttribute(conv_mma_kernel,
                         cudaFuncAttributeMaxDynamicSharedMemorySize, SMEM_BYTES);

    pack_x_kernel<<<25088, 256>>>(x);
    prep_a<<<576, 256>>>(w);
    conv_mma_kernel<<<dim3(4, 729), 256, SMEM_BYTES>>>(out);
}